// round 4
// baseline (speedup 1.0000x reference)
#include <cuda_runtime.h>
#include <cstdint>

// ---------------- problem dims ----------------
#define T_  64
#define N_  256
#define H_  1024
#define E_  1024
#define ZD  1024     // ZS*ZC
#define AD  48       // AS*AC
#define ZAD 1072     // ZD + AD
#define G3  3072     // 3*H

// ---------------- scratch (static device memory; no runtime alloc) ----------------
__device__ float g_h [T_ * N_ * H_];   // h slab [T,N,H]
__device__ float g_z [T_ * N_ * ZD];   // z slab [T,N,ZD] (one-hot fp32)
__device__ float g_za[N_ * ZAD];       // [z_prev | a_prev] per batch row
__device__ float g_gi[N_ * G3];        // gi = za @ Wih^T + bih
__device__ float g_gh[N_ * G3];        // gh = h  @ Whh^T + bhh

// ---------------- threefry2x32 (matches JAX exactly) ----------------
__host__ __device__ __forceinline__ void threefry2x32(
    uint32_t k0, uint32_t k1, uint32_t x0, uint32_t x1,
    uint32_t* o0, uint32_t* o1)
{
    uint32_t ks0 = k0, ks1 = k1, ks2 = k0 ^ k1 ^ 0x1BD11BDAu;
    x0 += ks0; x1 += ks1;
#define TF_R(r) { x0 += x1; x1 = (x1 << (r)) | (x1 >> (32 - (r))); x1 ^= x0; }
    TF_R(13) TF_R(15) TF_R(26) TF_R(6)
    x0 += ks1; x1 += ks2 + 1u;
    TF_R(17) TF_R(29) TF_R(16) TF_R(24)
    x0 += ks2; x1 += ks0 + 2u;
    TF_R(13) TF_R(15) TF_R(26) TF_R(6)
    x0 += ks0; x1 += ks1 + 3u;
    TF_R(17) TF_R(29) TF_R(16) TF_R(24)
    x0 += ks1; x1 += ks2 + 4u;
    TF_R(13) TF_R(15) TF_R(26) TF_R(6)
    x0 += ks2; x1 += ks0 + 5u;
#undef TF_R
    *o0 = x0; *o1 = x1;
}

// ---------------- GEMM: C[M,N] = A_cat[M,K] * B[K,N] + bias  (B row-major, N contiguous)
// A is a concatenation of two row sources: k < K1 -> A1 (row stride sA1), else A2 (stride sA2).
// Requires: M%64==0, N%64==0, K%16==0, K1%16==0.
__global__ __launch_bounds__(256) void gemm_nn_cat(
    const float* __restrict__ A1, const float* __restrict__ A2,
    const float* __restrict__ B,  const float* __restrict__ bias,
    float* __restrict__ C,
    int M, int N, int K, int K1, int sA1, int sA2)
{
    __shared__ float As[16][68];
    __shared__ float Bs[16][68];
    const int bm = blockIdx.y * 64, bn = blockIdx.x * 64;
    const int tid  = threadIdx.x;
    const int tm   = tid >> 4, tn = tid & 15;
    const int arow = tid >> 2, akk = (tid & 3) * 4;
    const int brow = tid >> 4, bnn = (tid & 15) * 4;

    float acc[4][4];
#pragma unroll
    for (int i = 0; i < 4; i++)
#pragma unroll
        for (int j = 0; j < 4; j++) acc[i][j] = 0.f;

    for (int k0 = 0; k0 < K; k0 += 16) {
        const float* Ap;
        if (k0 < K1) Ap = A1 + (size_t)(bm + arow) * sA1 + k0 + akk;
        else         Ap = A2 + (size_t)(bm + arow) * sA2 + (k0 - K1) + akk;
        float4 av = *(const float4*)Ap;
        As[akk + 0][arow] = av.x; As[akk + 1][arow] = av.y;
        As[akk + 2][arow] = av.z; As[akk + 3][arow] = av.w;

        float4 bv = *(const float4*)(B + (size_t)(k0 + brow) * N + bn + bnn);
        *(float4*)&Bs[brow][bnn] = bv;
        __syncthreads();
#pragma unroll
        for (int kk = 0; kk < 16; kk++) {
            float4 a = *(const float4*)&As[kk][tm * 4];
            float4 b = *(const float4*)&Bs[kk][tn * 4];
            float aa[4] = {a.x, a.y, a.z, a.w};
            float bb[4] = {b.x, b.y, b.z, b.w};
#pragma unroll
            for (int i = 0; i < 4; i++)
#pragma unroll
                for (int j = 0; j < 4; j++)
                    acc[i][j] = fmaf(aa[i], bb[j], acc[i][j]);
        }
        __syncthreads();
    }
#pragma unroll
    for (int i = 0; i < 4; i++) {
        float* Cp = C + (size_t)(bm + tm * 4 + i) * N + bn + tn * 4;
#pragma unroll
        for (int j = 0; j < 4; j++) Cp[j] = acc[i][j] + bias[bn + tn * 4 + j];
    }
}

// ---------------- GEMM: C[M,Nn] = A[M,K] * B[Nn,K]^T + bias  (both K-contiguous)
__global__ __launch_bounds__(256) void gemm_nt(
    const float* __restrict__ A, const float* __restrict__ B,
    const float* __restrict__ bias, float* __restrict__ C,
    int M, int Nn, int K, int lda, int ldb, int ldc)
{
    __shared__ float As[16][68];
    __shared__ float Bs[16][68];
    const int bm = blockIdx.y * 64, bn = blockIdx.x * 64;
    const int tid  = threadIdx.x;
    const int tm   = tid >> 4, tn = tid & 15;
    const int arow = tid >> 2, akk = (tid & 3) * 4;

    float acc[4][4];
#pragma unroll
    for (int i = 0; i < 4; i++)
#pragma unroll
        for (int j = 0; j < 4; j++) acc[i][j] = 0.f;

    for (int k0 = 0; k0 < K; k0 += 16) {
        float4 av = *(const float4*)(A + (size_t)(bm + arow) * lda + k0 + akk);
        As[akk + 0][arow] = av.x; As[akk + 1][arow] = av.y;
        As[akk + 2][arow] = av.z; As[akk + 3][arow] = av.w;
        float4 bv = *(const float4*)(B + (size_t)(bn + arow) * ldb + k0 + akk);
        Bs[akk + 0][arow] = bv.x; Bs[akk + 1][arow] = bv.y;
        Bs[akk + 2][arow] = bv.z; Bs[akk + 3][arow] = bv.w;
        __syncthreads();
#pragma unroll
        for (int kk = 0; kk < 16; kk++) {
            float4 a = *(const float4*)&As[kk][tm * 4];
            float4 b = *(const float4*)&Bs[kk][tn * 4];
            float aa[4] = {a.x, a.y, a.z, a.w};
            float bb[4] = {b.x, b.y, b.z, b.w};
#pragma unroll
            for (int i = 0; i < 4; i++)
#pragma unroll
                for (int j = 0; j < 4; j++)
                    acc[i][j] = fmaf(aa[i], bb[j], acc[i][j]);
        }
        __syncthreads();
    }
#pragma unroll
    for (int i = 0; i < 4; i++) {
        float* Cp = C + (size_t)(bm + tm * 4 + i) * ldc + bn + tn * 4;
#pragma unroll
        for (int j = 0; j < 4; j++) Cp[j] = acc[i][j] + bias[bn + tn * 4 + j];
    }
}

// ---------------- GRU gate fusion ----------------
__global__ __launch_bounds__(256) void gru_gate(
    const float* __restrict__ hprev, float* __restrict__ hout)
{
    int idx = blockIdx.x * blockDim.x + threadIdx.x;   // 0 .. N*H-1
    int n = idx >> 10, j = idx & 1023;
    const float* gin = g_gi + n * G3;
    const float* ghn = g_gh + n * G3;
    float r  = 1.f / (1.f + expf(-(gin[j]        + ghn[j])));
    float u  = 1.f / (1.f + expf(-(gin[j + 1024] + ghn[j + 1024])));
    float nn = tanhf(gin[j + 2048] + r * ghn[j + 2048]);
    hout[idx] = (1.f - u) * nn + u * hprev[idx];
}

// ---------------- copy h0 into slab ----------------
__global__ void copy_h0(const float* __restrict__ h0)
{
    int i = blockIdx.x * blockDim.x + threadIdx.x;
    g_h[i] = h0[i];
}

// ---------------- straight-through categorical sampler ----------------
// One warp per (n, s) row of 32 categories. Reproduces JAX's
// argmax(logits + gumbel) with jax_threefry_partitionable=True semantics:
// (b1, b2) = threefry2x32(key, hi=0, lo=i);  bits32[i] = b1 ^ b2.
// Also builds za for the next step: z one-hot + copy of a[t].
__global__ __launch_bounds__(256) void sampler(
    const float* __restrict__ zl,     // [N, ZD] logits (z_prior slab at t)
    float* __restrict__ z_out,        // [N, ZD] one-hot out (z slab at t)
    const float* __restrict__ a_t,    // [N, AD]
    uint32_t k0, uint32_t k1)
{
    const int warp = (blockIdx.x * blockDim.x + threadIdx.x) >> 5;  // 0..8191
    const int lane = threadIdx.x & 31;
    const int n = warp >> 5;
    const int s = warp & 31;
    const int i = n * 1024 + s * 32 + lane;      // flat index into (N,ZS,ZC)

    uint32_t r0, r1;
    threefry2x32(k0, k1, 0u, (uint32_t)i, &r0, &r1);
    uint32_t bits = r0 ^ r1;   // partitionable 32-bit path XORs the two outputs

    uint32_t mant = bits >> 9;
    float f = __uint_as_float(mant | 0x3f800000u) - 1.0f;  // [0,1)
    float u = (mant == 0u) ? 1.17549435e-38f : f;          // minval = f32 tiny
    float g = -logf(-logf(u));
    float v = zl[i] + g;

    // warp argmax, first-index tie-break (JAX argmax semantics)
    float bv = v; int bi = lane;
#pragma unroll
    for (int off = 16; off; off >>= 1) {
        float ov = __shfl_xor_sync(0xffffffffu, bv, off);
        int   oi = __shfl_xor_sync(0xffffffffu, bi, off);
        if (ov > bv || (ov == bv && oi < bi)) { bv = ov; bi = oi; }
    }
    float zv = (lane == bi) ? 1.0f : 0.0f;
    z_out[i] = zv;
    g_za[n * ZAD + s * 32 + lane] = zv;
    int ai = s * 32 + lane;
    if (ai < AD) g_za[n * ZAD + ZD + ai] = a_t[n * AD + ai];
}

// ---------------- reward / continue heads (N=1 GEMVs) ----------------
__global__ __launch_bounds__(256) void rc_kernel(
    const float* __restrict__ h, const float* __restrict__ rW,
    const float* __restrict__ cW, const float* __restrict__ cb,
    float* __restrict__ r_out, float* __restrict__ c_out, int rows)
{
    int w = (blockIdx.x * blockDim.x + threadIdx.x) >> 5;
    int lane = threadIdx.x & 31;
    if (w >= rows) return;
    const float* hr = h + (size_t)w * H_;
    float sr = 0.f, sc = 0.f;
    for (int k = lane; k < H_; k += 32) {
        float hv = hr[k];
        sr = fmaf(hv, rW[k], sr);
        sc = fmaf(hv, cW[k], sc);
    }
#pragma unroll
    for (int off = 16; off; off >>= 1) {
        sr += __shfl_xor_sync(0xffffffffu, sr, off);
        sc += __shfl_xor_sync(0xffffffffu, sc, off);
    }
    if (lane == 0) { r_out[w] = sr; c_out[w] = sc + cb[0]; }
}

// ---------------- host: split(key(42), T) — fold-in (partitionable) path ----------------
static void host_split_keys(uint32_t keys[T_][2])
{
    // keys[t] = threefry2x32((0,42), hi=0, lo=t)  (both outputs)
    for (int t = 0; t < T_; t++) {
        uint32_t a, b;
        threefry2x32(0u, 42u, 0u, (uint32_t)t, &a, &b);
        keys[t][0] = a; keys[t][1] = b;
    }
}

extern "C" void kernel_launch(void* const* d_in, const int* in_sizes, int n_in,
                              void* d_out, int out_size)
{
    const float* x      = (const float*)d_in[0];   // [T,N,32,32] == e
    const float* a      = (const float*)d_in[1];   // [T,N,6,8]
    const float* h0     = (const float*)d_in[2];   // [N,H]
    const float* enc_W  = (const float*)d_in[3];   // [2048,1024]
    const float* enc_b  = (const float*)d_in[4];
    const float* Wih    = (const float*)d_in[5];   // [3072,1072]
    const float* Whh    = (const float*)d_in[6];   // [3072,1024]
    const float* bih    = (const float*)d_in[7];
    const float* bhh    = (const float*)d_in[8];
    const float* dec_W  = (const float*)d_in[9];   // [2048,1024]
    const float* dec_b  = (const float*)d_in[10];
    const float* dyn_W  = (const float*)d_in[11];  // [1024,1024]
    const float* dyn_b  = (const float*)d_in[12];
    const float* rew_W  = (const float*)d_in[13];  // [1024,1]
    const float* con_W  = (const float*)d_in[14];  // [1024,1]
    const float* con_b  = (const float*)d_in[15];

    float* out = (float*)d_out;
    const size_t X0  = 0;
    const size_t R0  = (size_t)T_ * N_ * ZD;        // after x_logits
    const size_t C0  = R0 + (size_t)T_ * N_;
    const size_t ZP0 = C0 + (size_t)T_ * N_;
    const size_t ZQ0 = ZP0 + (size_t)T_ * N_ * ZD;

    uint32_t keys[T_][2];
    host_split_keys(keys);

    float* hslab; float* zslab;
    cudaGetSymbolAddress((void**)&hslab, g_h);
    cudaGetSymbolAddress((void**)&zslab, g_z);
    float* gi; float* gh; float* za;
    cudaGetSymbolAddress((void**)&gi, g_gi);
    cudaGetSymbolAddress((void**)&gh, g_gh);
    cudaGetSymbolAddress((void**)&za, g_za);

    // h slab[0] = h0
    copy_h0<<<(N_ * H_) / 256, 256>>>(h0);

    // ---- t = 0: encode(h0, e0) -> z_prior[0]; sample z0 (fills za with z0, a0)
    {
        dim3 g(ZD / 64, N_ / 64);
        gemm_nn_cat<<<g, 256>>>(hslab, x, enc_W, enc_b,
                                out + ZP0, N_, ZD, H_ + E_, H_, H_, E_);
        sampler<<<(N_ * ZD / 32) / 8, 256>>>(out + ZP0, zslab, a, keys[0][0], keys[0][1]);
    }

    // ---- t = 1 .. T-1
    for (int t = 1; t < T_; t++) {
        const float* hprev = hslab + (size_t)(t - 1) * N_ * H_;
        float* hcur = hslab + (size_t)t * N_ * H_;
        float* zp   = out + ZP0 + (size_t)t * N_ * ZD;
        float* zc   = zslab + (size_t)t * N_ * ZD;

        dim3 gg(G3 / 64, N_ / 64);
        gemm_nt<<<gg, 256>>>(za, Wih, bih, gi, N_, G3, ZAD, ZAD, ZAD, G3);
        gemm_nt<<<gg, 256>>>(hprev, Whh, bhh, gh, N_, G3, H_, H_, H_, G3);
        gru_gate<<<(N_ * H_) / 256, 256>>>(hprev, hcur);

        dim3 ge(ZD / 64, N_ / 64);
        gemm_nn_cat<<<ge, 256>>>(hcur, x + (size_t)t * N_ * E_, enc_W, enc_b,
                                 zp, N_, ZD, H_ + E_, H_, H_, E_);
        sampler<<<(N_ * ZD / 32) / 8, 256>>>(zp, zc, a + (size_t)t * N_ * AD,
                                             keys[t][0], keys[t][1]);
    }

    // ---- tail: decoder, dynamics, reward/continue over all T*N rows
    const int M = T_ * N_;  // 16384
    {
        dim3 g(ZD / 64, M / 64);
        gemm_nn_cat<<<g, 256>>>(hslab, zslab, dec_W, dec_b,
                                out + X0, M, ZD, H_ + ZD, H_, ZD, ZD);
    }
    {
        dim3 g(ZD / 64, M / 64);
        gemm_nn_cat<<<g, 256>>>(hslab, hslab, dyn_W, dyn_b,
                                out + ZQ0, M, ZD, H_, H_, H_, H_);
    }
    rc_kernel<<<(M * 32) / 256, 256>>>(hslab, rew_W, con_W, con_b,
                                       out + R0, out + C0, M);
}

// round 6
// speedup vs baseline: 1.4037x; 1.4037x over previous
#include <cuda_runtime.h>
#include <cstdint>

// ---------------- problem dims ----------------
#define T_  64
#define N_  256
#define H_  1024
#define E_  1024
#define ZD  1024     // ZS*ZC
#define AD  48       // AS*AC
#define ZAD 1072     // ZD + AD
#define G3  3072     // 3*H

// ---------------- scratch (static device memory; no runtime alloc) ----------------
__device__ float g_h  [T_ * N_ * H_];    // h slab [T,N,H]
__device__ float g_z  [T_ * N_ * ZD];    // z slab [T,N,ZD] (one-hot fp32)
__device__ float g_za [N_ * ZAD];        // [z_prev | a_prev] per batch row
__device__ float g_gip[2 * N_ * G3];     // split-K partials of za @ Wih^T
__device__ float g_ghp[2 * N_ * G3];     // split-K partials of h  @ Whh^T
__device__ float g_ep [4 * N_ * ZD];     // split-K partials of encoder

// ---------------- threefry2x32 (matches JAX exactly) ----------------
__host__ __device__ __forceinline__ void threefry2x32(
    uint32_t k0, uint32_t k1, uint32_t x0, uint32_t x1,
    uint32_t* o0, uint32_t* o1)
{
    uint32_t ks0 = k0, ks1 = k1, ks2 = k0 ^ k1 ^ 0x1BD11BDAu;
    x0 += ks0; x1 += ks1;
#define TF_R(r) { x0 += x1; x1 = (x1 << (r)) | (x1 >> (32 - (r))); x1 ^= x0; }
    TF_R(13) TF_R(15) TF_R(26) TF_R(6)
    x0 += ks1; x1 += ks2 + 1u;
    TF_R(17) TF_R(29) TF_R(16) TF_R(24)
    x0 += ks2; x1 += ks0 + 2u;
    TF_R(13) TF_R(15) TF_R(26) TF_R(6)
    x0 += ks0; x1 += ks1 + 3u;
    TF_R(17) TF_R(29) TF_R(16) TF_R(24)
    x0 += ks1; x1 += ks2 + 4u;
    TF_R(13) TF_R(15) TF_R(26) TF_R(6)
    x0 += ks2; x1 += ks0 + 5u;
#undef TF_R
    *o0 = x0; *o1 = x1;
}

// ============================================================================
// Fused NT GEMM for the GRU input/hidden projections, split-K2.
// blockIdx.z: bit1 = which gemm (0: gi = za@Wih^T, 1: gh = h@Whh^T), bit0 = k-chunk.
// 64x64 tile, 256 thr, 4x4 acc, double-buffered smem. No bias (folded into gate).
// ============================================================================
__global__ __launch_bounds__(256, 2) void step_nt_fused(
    const float* __restrict__ za, const float* __restrict__ hprev,
    const float* __restrict__ Wih, const float* __restrict__ Whh)
{
    __shared__ float As[2][16][68];
    __shared__ float Bs[2][16][68];
    const int g  = blockIdx.z >> 1;
    const int kc = blockIdx.z & 1;
    const float* A; const float* B; float* C; int lda, ktb, kte;
    if (g == 0) { A = za;    B = Wih; lda = ZAD; C = g_gip + kc * (N_ * G3); ktb = kc ? 34 : 0; kte = kc ? 67 : 34; }
    else        { A = hprev; B = Whh; lda = H_;  C = g_ghp + kc * (N_ * G3); ktb = kc ? 32 : 0; kte = kc ? 64 : 32; }

    const int bm = blockIdx.y * 64, bn = blockIdx.x * 64;
    const int tid = threadIdx.x;
    const int row = tid & 63, kq = (tid >> 6) * 4;   // conflict-free transpose store
    const int tm  = tid >> 4, tn = tid & 15;

    const float* Arow = A + (size_t)(bm + row) * lda + kq;
    const float* Brow = B + (size_t)(bn + row) * lda + kq;

    float acc[4][4];
#pragma unroll
    for (int i = 0; i < 4; i++)
#pragma unroll
        for (int j = 0; j < 4; j++) acc[i][j] = 0.f;

    float4 av = *(const float4*)(Arow + ktb * 16);
    float4 bv = *(const float4*)(Brow + ktb * 16);
    int buf = 0;
    As[0][kq + 0][row] = av.x; As[0][kq + 1][row] = av.y;
    As[0][kq + 2][row] = av.z; As[0][kq + 3][row] = av.w;
    Bs[0][kq + 0][row] = bv.x; Bs[0][kq + 1][row] = bv.y;
    Bs[0][kq + 2][row] = bv.z; Bs[0][kq + 3][row] = bv.w;
    __syncthreads();

    for (int kt = ktb; kt < kte; ++kt) {
        const bool more = (kt + 1 < kte);
        if (more) {
            av = *(const float4*)(Arow + (kt + 1) * 16);
            bv = *(const float4*)(Brow + (kt + 1) * 16);
        }
#pragma unroll
        for (int kk = 0; kk < 16; kk++) {
            float4 a = *(const float4*)&As[buf][kk][tm * 4];
            float4 b = *(const float4*)&Bs[buf][kk][tn * 4];
            float aa[4] = {a.x, a.y, a.z, a.w};
            float bb[4] = {b.x, b.y, b.z, b.w};
#pragma unroll
            for (int i = 0; i < 4; i++)
#pragma unroll
                for (int j = 0; j < 4; j++)
                    acc[i][j] = fmaf(aa[i], bb[j], acc[i][j]);
        }
        if (more) {
            int nb = buf ^ 1;
            As[nb][kq + 0][row] = av.x; As[nb][kq + 1][row] = av.y;
            As[nb][kq + 2][row] = av.z; As[nb][kq + 3][row] = av.w;
            Bs[nb][kq + 0][row] = bv.x; Bs[nb][kq + 1][row] = bv.y;
            Bs[nb][kq + 2][row] = bv.z; Bs[nb][kq + 3][row] = bv.w;
        }
        buf ^= 1;
        __syncthreads();
    }
#pragma unroll
    for (int i = 0; i < 4; i++) {
        float* Cp = C + (size_t)(bm + tm * 4 + i) * G3 + bn + tn * 4;
#pragma unroll
        for (int j = 0; j < 4; j++) Cp[j] = acc[i][j];
    }
}

// ============================================================================
// Encoder NN GEMM, split-K4. C_partial[kc] = A_chunk[256,512] @ W_chunk[512,1024].
// kc<2 reads h rows, kc>=2 reads e rows (both stride 1024). No bias (in sampler).
// ============================================================================
__global__ __launch_bounds__(256, 2) void enc_nn_split(
    const float* __restrict__ h, const float* __restrict__ e,
    const float* __restrict__ W)
{
    __shared__ float As[2][16][68];
    __shared__ float Bs[2][16][68];
    const int kc = blockIdx.z;
    const float* A = (kc < 2) ? h : e;
    const int koff = (kc & 1) * 512;             // within the source
    const int kW   = (kc < 2 ? 0 : 1024) + koff; // global k for W rows
    float* C = g_ep + kc * (N_ * ZD);

    const int bm = blockIdx.y * 64, bn = blockIdx.x * 64;
    const int tid = threadIdx.x;
    const int row = tid & 63, kq = (tid >> 6) * 4;  // A transpose-store
    const int bk = tid >> 4, bn4 = (tid & 15) * 4;  // B direct store
    const int tm = tid >> 4, tn = tid & 15;

    const float* Arow = A + (size_t)(bm + row) * 1024 + koff + kq;
    const float* Bbase = W + (size_t)kW * 1024 + bn;

    float acc[4][4];
#pragma unroll
    for (int i = 0; i < 4; i++)
#pragma unroll
        for (int j = 0; j < 4; j++) acc[i][j] = 0.f;

    float4 av = *(const float4*)(Arow);
    float4 bv = *(const float4*)(Bbase + (size_t)bk * 1024 + bn4);
    int buf = 0;
    As[0][kq + 0][row] = av.x; As[0][kq + 1][row] = av.y;
    As[0][kq + 2][row] = av.z; As[0][kq + 3][row] = av.w;
    *(float4*)&Bs[0][bk][bn4] = bv;
    __syncthreads();

    for (int kt = 0; kt < 32; ++kt) {
        const bool more = (kt + 1 < 32);
        if (more) {
            av = *(const float4*)(Arow + (kt + 1) * 16);
            bv = *(const float4*)(Bbase + (size_t)((kt + 1) * 16 + bk) * 1024 + bn4);
        }
#pragma unroll
        for (int kk = 0; kk < 16; kk++) {
            float4 a = *(const float4*)&As[buf][kk][tm * 4];
            float4 b = *(const float4*)&Bs[buf][kk][tn * 4];
            float aa[4] = {a.x, a.y, a.z, a.w};
            float bb[4] = {b.x, b.y, b.z, b.w};
#pragma unroll
            for (int i = 0; i < 4; i++)
#pragma unroll
                for (int j = 0; j < 4; j++)
                    acc[i][j] = fmaf(aa[i], bb[j], acc[i][j]);
        }
        if (more) {
            int nb = buf ^ 1;
            As[nb][kq + 0][row] = av.x; As[nb][kq + 1][row] = av.y;
            As[nb][kq + 2][row] = av.z; As[nb][kq + 3][row] = av.w;
            *(float4*)&Bs[nb][bk][bn4] = bv;
        }
        buf ^= 1;
        __syncthreads();
    }
#pragma unroll
    for (int i = 0; i < 4; i++) {
        float* Cp = C + (size_t)(bm + tm * 4 + i) * ZD + bn + tn * 4;
#pragma unroll
        for (int j = 0; j < 4; j++) Cp[j] = acc[i][j];
    }
}

// ============================================================================
// Tail NN GEMM: 128x128 tile, 256 thr, 8x8 acc, double-buffered, ktile=8.
// A rows: k<K1 from A1 else A2 (both row stride 1024). B [K,1024], bias added.
// ============================================================================
__global__ __launch_bounds__(256, 2) void tail_nn_128(
    const float* __restrict__ A1, const float* __restrict__ A2,
    const float* __restrict__ B,  const float* __restrict__ bias,
    float* __restrict__ C, int K, int K1)
{
    __shared__ float As[2][8][132];
    __shared__ float Bs[2][8][132];
    const int bm = blockIdx.y * 128, bn = blockIdx.x * 128;
    const int tid = threadIdx.x;
    const int arow = tid & 127, akq = (tid >> 7) * 4;   // 0 or 4
    const int bk = tid >> 5, bn4 = (tid & 31) * 4;
    const int tm = tid >> 4, tn = tid & 15;

    float acc[8][8];
#pragma unroll
    for (int i = 0; i < 8; i++)
#pragma unroll
        for (int j = 0; j < 8; j++) acc[i][j] = 0.f;

    const int nkt = K / 8;

    auto ldA = [&](int kt) -> float4 {
        int k = kt * 8 + akq;
        const float* Ap = (k < K1) ? (A1 + (size_t)(bm + arow) * 1024 + k)
                                   : (A2 + (size_t)(bm + arow) * 1024 + (k - K1));
        return *(const float4*)Ap;
    };
    auto ldB = [&](int kt) -> float4 {
        return *(const float4*)(B + (size_t)(kt * 8 + bk) * 1024 + bn + bn4);
    };

    float4 av = ldA(0);
    float4 bv = ldB(0);
    int buf = 0;
    As[0][akq + 0][arow] = av.x; As[0][akq + 1][arow] = av.y;
    As[0][akq + 2][arow] = av.z; As[0][akq + 3][arow] = av.w;
    *(float4*)&Bs[0][bk][bn4] = bv;
    __syncthreads();

    for (int kt = 0; kt < nkt; ++kt) {
        const bool more = (kt + 1 < nkt);
        if (more) { av = ldA(kt + 1); bv = ldB(kt + 1); }
#pragma unroll
        for (int kk = 0; kk < 8; kk++) {
            float4 a0 = *(const float4*)&As[buf][kk][tm * 8];
            float4 a1 = *(const float4*)&As[buf][kk][tm * 8 + 4];
            float4 b0 = *(const float4*)&Bs[buf][kk][tn * 8];
            float4 b1 = *(const float4*)&Bs[buf][kk][tn * 8 + 4];
            float aa[8] = {a0.x, a0.y, a0.z, a0.w, a1.x, a1.y, a1.z, a1.w};
            float bb[8] = {b0.x, b0.y, b0.z, b0.w, b1.x, b1.y, b1.z, b1.w};
#pragma unroll
            for (int i = 0; i < 8; i++)
#pragma unroll
                for (int j = 0; j < 8; j++)
                    acc[i][j] = fmaf(aa[i], bb[j], acc[i][j]);
        }
        if (more) {
            int nb = buf ^ 1;
            As[nb][akq + 0][arow] = av.x; As[nb][akq + 1][arow] = av.y;
            As[nb][akq + 2][arow] = av.z; As[nb][akq + 3][arow] = av.w;
            *(float4*)&Bs[nb][bk][bn4] = bv;
        }
        buf ^= 1;
        __syncthreads();
    }
#pragma unroll
    for (int i = 0; i < 8; i++) {
        float* Cp = C + (size_t)(bm + tm * 8 + i) * 1024 + bn + tn * 8;
#pragma unroll
        for (int j = 0; j < 8; j++) Cp[j] = acc[i][j] + bias[bn + tn * 8 + j];
    }
}

// ---------------- GRU gate fusion (+ split-K reduction + biases) ----------------
__global__ __launch_bounds__(256) void gru_gate2(
    const float* __restrict__ hprev, float* __restrict__ hout,
    const float* __restrict__ bih, const float* __restrict__ bhh)
{
    int idx = blockIdx.x * blockDim.x + threadIdx.x;   // 0 .. N*H-1
    int n = idx >> 10, j = idx & 1023;
    const float* gi0 = g_gip + (size_t)n * G3;
    const float* gi1 = g_gip + (size_t)N_ * G3 + (size_t)n * G3;
    const float* gh0 = g_ghp + (size_t)n * G3;
    const float* gh1 = g_ghp + (size_t)N_ * G3 + (size_t)n * G3;

    float ir = gi0[j]        + gi1[j]        + bih[j];
    float iu = gi0[j + 1024] + gi1[j + 1024] + bih[j + 1024];
    float in_= gi0[j + 2048] + gi1[j + 2048] + bih[j + 2048];
    float hr = gh0[j]        + gh1[j]        + bhh[j];
    float hu = gh0[j + 1024] + gh1[j + 1024] + bhh[j + 1024];
    float hn = gh0[j + 2048] + gh1[j + 2048] + bhh[j + 2048];

    float r  = 1.f / (1.f + expf(-(ir + hr)));
    float u  = 1.f / (1.f + expf(-(iu + hu)));
    float nn = tanhf(in_ + r * hn);
    hout[idx] = (1.f - u) * nn + u * hprev[idx];
}

// ---------------- copy h0 into slab ----------------
__global__ void copy_h0(const float* __restrict__ h0)
{
    int i = blockIdx.x * blockDim.x + threadIdx.x;
    g_h[i] = h0[i];
}

// ---------------- sampler (+ encoder split-K reduction + bias) ----------------
// One warp per (n, s) row. Sums 4 encoder partials + enc_b -> logits, writes
// z_prior out, draws JAX partitionable-threefry gumbel, warp-argmax -> one-hot,
// writes z slab and za for next step.
__global__ __launch_bounds__(256) void sampler2(
    float* __restrict__ zp_out,       // [N, ZD] z_prior logits out
    float* __restrict__ z_out,        // [N, ZD] one-hot out (z slab at t)
    const float* __restrict__ enc_b,  // [ZD]
    const float* __restrict__ a_t,    // [N, AD]
    uint32_t k0, uint32_t k1)
{
    const int warp = (blockIdx.x * blockDim.x + threadIdx.x) >> 5;
    const int lane = threadIdx.x & 31;
    const int n = warp >> 5;
    const int s = warp & 31;
    const int i = n * 1024 + s * 32 + lane;

    float l = g_ep[i] + g_ep[N_ * ZD + i] + g_ep[2 * N_ * ZD + i]
            + g_ep[3 * N_ * ZD + i] + enc_b[s * 32 + lane];
    zp_out[i] = l;

    uint32_t r0, r1;
    threefry2x32(k0, k1, 0u, (uint32_t)i, &r0, &r1);
    uint32_t bits = r0 ^ r1;

    uint32_t mant = bits >> 9;
    float f = __uint_as_float(mant | 0x3f800000u) - 1.0f;
    float u = (mant == 0u) ? 1.17549435e-38f : f;
    float g = -logf(-logf(u));
    float v = l + g;

    float bv = v; int bi = lane;
#pragma unroll
    for (int off = 16; off; off >>= 1) {
        float ov = __shfl_xor_sync(0xffffffffu, bv, off);
        int   oi = __shfl_xor_sync(0xffffffffu, bi, off);
        if (ov > bv || (ov == bv && oi < bi)) { bv = ov; bi = oi; }
    }
    float zv = (lane == bi) ? 1.0f : 0.0f;
    z_out[i] = zv;
    g_za[n * ZAD + s * 32 + lane] = zv;
    int ai = s * 32 + lane;
    if (ai < AD) g_za[n * ZAD + ZD + ai] = a_t[n * AD + ai];
}

// ---------------- reward / continue heads ----------------
__global__ __launch_bounds__(256) void rc_kernel(
    const float* __restrict__ h, const float* __restrict__ rW,
    const float* __restrict__ cW, const float* __restrict__ cb,
    float* __restrict__ r_out, float* __restrict__ c_out, int rows)
{
    int w = (blockIdx.x * blockDim.x + threadIdx.x) >> 5;
    int lane = threadIdx.x & 31;
    if (w >= rows) return;
    const float* hr = h + (size_t)w * H_;
    float sr = 0.f, sc = 0.f;
    for (int k = lane; k < H_; k += 32) {
        float hv = hr[k];
        sr = fmaf(hv, rW[k], sr);
        sc = fmaf(hv, cW[k], sc);
    }
#pragma unroll
    for (int off = 16; off; off >>= 1) {
        sr += __shfl_xor_sync(0xffffffffu, sr, off);
        sc += __shfl_xor_sync(0xffffffffu, sc, off);
    }
    if (lane == 0) { r_out[w] = sr; c_out[w] = sc + cb[0]; }
}

// ---------------- host: split(key(42), T) — fold-in (partitionable) path ----------------
static void host_split_keys(uint32_t keys[T_][2])
{
    for (int t = 0; t < T_; t++) {
        uint32_t a, b;
        threefry2x32(0u, 42u, 0u, (uint32_t)t, &a, &b);
        keys[t][0] = a; keys[t][1] = b;
    }
}

extern "C" void kernel_launch(void* const* d_in, const int* in_sizes, int n_in,
                              void* d_out, int out_size)
{
    const float* x      = (const float*)d_in[0];
    const float* a      = (const float*)d_in[1];
    const float* h0     = (const float*)d_in[2];
    const float* enc_W  = (const float*)d_in[3];
    const float* enc_b  = (const float*)d_in[4];
    const float* Wih    = (const float*)d_in[5];
    const float* Whh    = (const float*)d_in[6];
    const float* bih    = (const float*)d_in[7];
    const float* bhh    = (const float*)d_in[8];
    const float* dec_W  = (const float*)d_in[9];
    const float* dec_b  = (const float*)d_in[10];
    const float* dyn_W  = (const float*)d_in[11];
    const float* dyn_b  = (const float*)d_in[12];
    const float* rew_W  = (const float*)d_in[13];
    const float* con_W  = (const float*)d_in[14];
    const float* con_b  = (const float*)d_in[15];

    float* out = (float*)d_out;
    const size_t X0  = 0;
    const size_t R0  = (size_t)T_ * N_ * ZD;
    const size_t C0  = R0 + (size_t)T_ * N_;
    const size_t ZP0 = C0 + (size_t)T_ * N_;
    const size_t ZQ0 = ZP0 + (size_t)T_ * N_ * ZD;

    uint32_t keys[T_][2];
    host_split_keys(keys);

    float* hslab; float* zslab; float* za;
    cudaGetSymbolAddress((void**)&hslab, g_h);
    cudaGetSymbolAddress((void**)&zslab, g_z);
    cudaGetSymbolAddress((void**)&za, g_za);

    copy_h0<<<(N_ * H_) / 256, 256>>>(h0);

    // ---- t = 0: encoder(h0, e0) split-K -> sampler
    enc_nn_split<<<dim3(ZD / 64, N_ / 64, 4), 256>>>(hslab, x, enc_W);
    sampler2<<<(N_ * ZD / 32) / 8, 256>>>(out + ZP0, zslab, enc_b, a,
                                          keys[0][0], keys[0][1]);

    // ---- t = 1 .. T-1
    for (int t = 1; t < T_; t++) {
        const float* hprev = hslab + (size_t)(t - 1) * N_ * H_;
        float* hcur = hslab + (size_t)t * N_ * H_;
        float* zp   = out + ZP0 + (size_t)t * N_ * ZD;
        float* zc   = zslab + (size_t)t * N_ * ZD;

        step_nt_fused<<<dim3(G3 / 64, N_ / 64, 4), 256>>>(za, hprev, Wih, Whh);
        gru_gate2<<<(N_ * H_) / 256, 256>>>(hprev, hcur, bih, bhh);
        enc_nn_split<<<dim3(ZD / 64, N_ / 64, 4), 256>>>(hcur, x + (size_t)t * N_ * E_, enc_W);
        sampler2<<<(N_ * ZD / 32) / 8, 256>>>(zp, zc, enc_b, a + (size_t)t * N_ * AD,
                                              keys[t][0], keys[t][1]);
    }

    // ---- tail: decoder (cat h,z; K=2048), dynamics (K=1024), reward/continue
    tail_nn_128<<<dim3(ZD / 128, (T_ * N_) / 128), 256>>>(
        hslab, zslab, dec_W, dec_b, out + X0, 2048, 1024);
    tail_nn_128<<<dim3(ZD / 128, (T_ * N_) / 128), 256>>>(
        hslab, hslab, dyn_W, dyn_b, out + ZQ0, 1024, 1024);
    rc_kernel<<<((T_ * N_) * 32) / 256, 256>>>(hslab, rew_W, con_W, con_b,
                                               out + R0, out + C0, T_ * N_);
}